// round 2
// baseline (speedup 1.0000x reference)
#include <cuda_runtime.h>
#include <cuda_bf16.h>
#include <math.h>

// Problem constants
#define B_  4
#define C_  64
#define HA_ 512
#define WA_ 512
#define N_  256
#define HB_ 32
#define WB_ 32
#define PLANE_ (HA_ * WA_)          // 262144
#define POS_   (HB_ * WB_)          // 1024 positions per patch
#define THREADS_ 256
#define POS_PER_THREAD_ 4
#define CSPLIT_ 4
#define CPB_ (C_ / CSPLIT_)         // 16 channels per block

__global__ __launch_bounds__(THREADS_)
void aerial_patch_sampler_kernel(const float* __restrict__ feat,
                                 const float* __restrict__ pose,
                                 float* __restrict__ out) {
    const int n   = blockIdx.x;      // patch index
    const int b   = blockIdx.y;      // batch index
    const int cz  = blockIdx.z;      // channel slice
    const int tid = threadIdx.x;

    // Pose for this (b, n): broadcast loads
    const float* pp = pose + ((size_t)b * N_ + n) * 3;
    const float u_off = pp[0];
    const float v_off = pp[1];
    const float theta = pp[2];
    float s, c;
    sincosf(theta, &s, &c);
    const float cos_r = c;       // cos(-theta) = cos(theta)
    const float sin_r = -s;      // sin(-theta) = -sin(theta)

    // Per-position constants. Position mapping: pos = k*256 + tid, so that
    // within a warp, consecutive lanes sample consecutive wb (1 px apart in
    // the rotated grid) -> warp-wide gather LDGs touch few cache lines.
    int   idx00[POS_PER_THREAD_], idx10[POS_PER_THREAD_];
    int   idx01[POS_PER_THREAD_], idx11[POS_PER_THREAD_];
    float w00[POS_PER_THREAD_], w10[POS_PER_THREAD_];
    float w01[POS_PER_THREAD_], w11[POS_PER_THREAD_];

    #pragma unroll
    for (int k = 0; k < POS_PER_THREAD_; ++k) {
        const int pos = k * THREADS_ + tid;
        const int hb = pos >> 5;         // / WB_
        const int wb = pos & 31;         // % WB_

        const float gu0 = (float)(HB_ - 1 - hb);
        const float gv0 = (float)(wb - WB_ / 2);

        const float gu = u_off + cos_r * gu0 - sin_r * gv0;
        const float gv = v_off + sin_r * gu0 + cos_r * gv0;

        // normalized coords (FEATURE_SCALE = 1)
        float gx = (gu + 0.5f) * (2.0f / (float)WA_) - 1.0f;
        float gy = (gv + 0.5f) * (2.0f / (float)HA_) - 1.0f;
        const bool valid = (fabsf(gx) < 1.0f) && (fabsf(gy) < 1.0f);
        if (!valid) { gx = 2.0f; gy = 2.0f; }

        // unnormalize (align_corners=False)
        const float ix = ((gx + 1.0f) * (float)WA_ - 1.0f) * 0.5f;
        const float iy = ((gy + 1.0f) * (float)HA_ - 1.0f) * 0.5f;

        const float x0f = floorf(ix);
        const float y0f = floorf(iy);
        const float wx1 = ix - x0f;
        const float wx0 = 1.0f - wx1;
        const float wy1 = iy - y0f;
        const float wy0 = 1.0f - wy1;

        const int x0 = (int)x0f;
        const int y0 = (int)y0f;
        const int x1 = x0 + 1;
        const int y1 = y0 + 1;

        const bool vx0 = (x0 >= 0) && (x0 < WA_);
        const bool vx1 = (x1 >= 0) && (x1 < WA_);
        const bool vy0 = (y0 >= 0) && (y0 < HA_);
        const bool vy1 = (y1 >= 0) && (y1 < HA_);

        const int x0c = min(max(x0, 0), WA_ - 1);
        const int x1c = min(max(x1, 0), WA_ - 1);
        const int y0c = min(max(y0, 0), HA_ - 1);
        const int y1c = min(max(y1, 0), HA_ - 1);

        idx00[k] = y0c * WA_ + x0c;
        idx10[k] = y0c * WA_ + x1c;
        idx01[k] = y1c * WA_ + x0c;
        idx11[k] = y1c * WA_ + x1c;

        w00[k] = (vx0 && vy0) ? (wx0 * wy0) : 0.0f;
        w10[k] = (vx1 && vy0) ? (wx1 * wy0) : 0.0f;
        w01[k] = (vx0 && vy1) ? (wx0 * wy1) : 0.0f;
        w11[k] = (vx1 && vy1) ? (wx1 * wy1) : 0.0f;
    }

    const int ch0 = cz * CPB_;
    const float* plane = feat + (size_t)b * C_ * PLANE_ + (size_t)ch0 * PLANE_;
    float* outp = out + (((size_t)b * N_ + n) * C_ + ch0) * (size_t)POS_;

    #pragma unroll 2
    for (int ch = 0; ch < CPB_; ++ch) {
        const float* base = plane + (size_t)ch * PLANE_;
        float* outc = outp + (size_t)ch * POS_;
        float acc[POS_PER_THREAD_];
        #pragma unroll
        for (int k = 0; k < POS_PER_THREAD_; ++k) {
            const float v00 = __ldg(base + idx00[k]);
            const float v10 = __ldg(base + idx10[k]);
            const float v01 = __ldg(base + idx01[k]);
            const float v11 = __ldg(base + idx11[k]);
            acc[k] = v00 * w00[k] + v10 * w10[k] + v01 * w01[k] + v11 * w11[k];
        }
        #pragma unroll
        for (int k = 0; k < POS_PER_THREAD_; ++k) {
            outc[k * THREADS_ + tid] = acc[k];
        }
    }
}

extern "C" void kernel_launch(void* const* d_in, const int* in_sizes, int n_in,
                              void* d_out, int out_size) {
    const float* aer_feat = (const float*)d_in[0];
    const float* pose_uvr = (const float*)d_in[1];
    float* out = (float*)d_out;

    dim3 grid(N_, B_, CSPLIT_);
    dim3 block(THREADS_);
    aerial_patch_sampler_kernel<<<grid, block>>>(aer_feat, pose_uvr, out);
}

// round 4
// speedup vs baseline: 1.1938x; 1.1938x over previous
#include <cuda_runtime.h>
#include <cuda_bf16.h>
#include <math.h>
#include <stdint.h>

// Problem constants
#define B_  4
#define C_  64
#define HA_ 512
#define WA_ 512
#define N_  256
#define HB_ 32
#define WB_ 32
#define PLANE_ (HA_ * WA_)
#define POS_   (HB_ * WB_)
#define THREADS_ 256
#define PPT_ 4                 // positions per thread

#define PITCH_ 66              // tile pitch in words; 66 % 32 == 2 (bank-friendly)
#define MAXH_ 48
#define TILE_WORDS_ (MAXH_ * PITCH_)

__device__ __forceinline__ void cp_async8(unsigned dst, const void* src) {
    asm volatile("cp.async.ca.shared.global [%0], [%1], 8;\n" :: "r"(dst), "l"(src));
}
__device__ __forceinline__ void cp_commit() { asm volatile("cp.async.commit_group;\n"); }
__device__ __forceinline__ void cp_wait1()  { asm volatile("cp.async.wait_group 1;\n"); }
__device__ __forceinline__ void cp_wait0()  { asm volatile("cp.async.wait_group 0;\n"); }

// Replicate the reference's float chain: grid coord -> normalized -> pixel coord
__device__ __forceinline__ float ref_chain(float g, float sz) {
    float gx = (g + 0.5f) * (2.0f / sz) - 1.0f;
    return ((gx + 1.0f) * sz - 1.0f) * 0.5f;
}

__global__ __launch_bounds__(THREADS_)
void aerial_patch_sampler_kernel(const float* __restrict__ feat,
                                 const float* __restrict__ pose,
                                 float* __restrict__ out) {
    __shared__ float tile[2][TILE_WORDS_];

    const int n   = blockIdx.x;
    const int b   = blockIdx.y;
    const int tid = threadIdx.x;

    const float* pp = pose + ((size_t)b * N_ + n) * 3;
    const float u_off = pp[0];
    const float v_off = pp[1];
    const float theta = pp[2];
    float s, c;
    sincosf(theta, &s, &c);
    const float cos_r = c;
    const float sin_r = -s;

    // ---- bounding box of the rotated patch (separable over corner terms) ----
    // gu = u + cos_r*gu0 - sin_r*gv0, gu0 in [0,31], gv0 in [-16,15]
    const float a1 = cos_r * 31.0f;
    const float a2 = -sin_r * (-16.0f), a3 = -sin_r * 15.0f;
    const float gu_min = u_off + fminf(0.0f, a1) + fminf(a2, a3);
    const float gu_max = u_off + fmaxf(0.0f, a1) + fmaxf(a2, a3);
    const float b1 = sin_r * 31.0f;
    const float b2 = cos_r * (-16.0f), b3 = cos_r * 15.0f;
    const float gv_min = v_off + fminf(0.0f, b1) + fminf(b2, b3);
    const float gv_max = v_off + fmaxf(0.0f, b1) + fmaxf(b2, b3);

    // Run the extremes through the same float chain the samples use (monotone),
    // so every valid sample's taps provably land inside the loaded tile.
    const float ixm = ref_chain(gu_min, (float)WA_);
    const float ixM = ref_chain(gu_max, (float)WA_);
    const float iym = ref_chain(gv_min, (float)HA_);
    const float iyM = ref_chain(gv_max, (float)HA_);

    int x_lo = min(max((int)floorf(ixm), 0), WA_ - 1) & ~1;   // 8B-align source
    int x_hi = min(max((int)floorf(ixM) + 1, 0), WA_ - 1);
    int y_lo = min(max((int)floorf(iym), 0), HA_ - 1);
    int y_hi = min(max((int)floorf(iyM) + 1, 0), HA_ - 1);
    if (x_hi < x_lo) x_hi = x_lo;
    if (y_hi < y_lo) y_hi = y_lo;
    int H = min(y_hi - y_lo + 1, MAXH_);
    int x_cov_hi = min(x_hi | 1, WA_ - 1);                    // stay inside the row
    if (x_cov_hi < x_lo + 1) x_cov_hi = x_lo + 1;             // >=1 granule
    int n8 = min(((x_cov_hi - x_lo) >> 1) + 1, PITCH_ / 2);   // 8B granules per row
    const int txmax = x_cov_hi - x_lo;                        // last loaded col
    const int tymax = H - 1;                                  // last loaded row

    // ---- per-thread sample parameters (channel-invariant) ----
    int   o00[PPT_], o10[PPT_], o01[PPT_], o11[PPT_];
    float w00[PPT_], w10[PPT_], w01[PPT_], w11[PPT_];

    #pragma unroll
    for (int k = 0; k < PPT_; ++k) {
        const int pos = k * THREADS_ + tid;
        const int hb = pos >> 5;
        const int wb = pos & 31;

        const float gu0 = (float)(HB_ - 1 - hb);
        const float gv0 = (float)(wb - WB_ / 2);
        const float gu = u_off + cos_r * gu0 - sin_r * gv0;
        const float gv = v_off + sin_r * gu0 + cos_r * gv0;

        float gx = (gu + 0.5f) * (2.0f / (float)WA_) - 1.0f;
        float gy = (gv + 0.5f) * (2.0f / (float)HA_) - 1.0f;
        const bool valid = (fabsf(gx) < 1.0f) && (fabsf(gy) < 1.0f);
        if (!valid) { gx = 2.0f; gy = 2.0f; }

        const float ix = ((gx + 1.0f) * (float)WA_ - 1.0f) * 0.5f;
        const float iy = ((gy + 1.0f) * (float)HA_ - 1.0f) * 0.5f;

        const float x0f = floorf(ix);
        const float y0f = floorf(iy);
        const float wx1 = ix - x0f;
        const float wx0 = 1.0f - wx1;
        const float wy1 = iy - y0f;
        const float wy0 = 1.0f - wy1;

        const int x0 = (int)x0f, y0 = (int)y0f;
        const int x1 = x0 + 1,   y1 = y0 + 1;

        const bool vx0 = (x0 >= 0) && (x0 < WA_);
        const bool vx1 = (x1 >= 0) && (x1 < WA_);
        const bool vy0 = (y0 >= 0) && (y0 < HA_);
        const bool vy1 = (y1 >= 0) && (y1 < HA_);

        // tile-relative coords, clamped into the LOADED region (zero-weight
        // taps may land anywhere; clamping keeps them on real loaded data)
        const int tx0 = min(max(min(max(x0, 0), WA_ - 1) - x_lo, 0), txmax);
        const int tx1 = min(max(min(max(x1, 0), WA_ - 1) - x_lo, 0), txmax);
        const int ty0 = min(max(min(max(y0, 0), HA_ - 1) - y_lo, 0), tymax);
        const int ty1 = min(max(min(max(y1, 0), HA_ - 1) - y_lo, 0), tymax);

        o00[k] = ty0 * PITCH_ + tx0;
        o10[k] = ty0 * PITCH_ + tx1;
        o01[k] = ty1 * PITCH_ + tx0;
        o11[k] = ty1 * PITCH_ + tx1;

        w00[k] = (vx0 && vy0) ? (wx0 * wy0) : 0.0f;
        w10[k] = (vx1 && vy0) ? (wx1 * wy0) : 0.0f;
        w01[k] = (vx0 && vy1) ? (wx0 * wy1) : 0.0f;
        w11[k] = (vx1 && vy1) ? (wx1 * wy1) : 0.0f;
    }

    // ---- channel loop with double-buffered cp.async tile staging ----
    const float* plane0 = feat + (size_t)b * C_ * PLANE_ + (size_t)y_lo * WA_ + x_lo;
    float* outp = out + (((size_t)b * N_ + n) * C_) * (size_t)POS_;

    const unsigned smem0 = (unsigned)__cvta_generic_to_shared(&tile[0][0]);
    const unsigned smem1 = (unsigned)__cvta_generic_to_shared(&tile[1][0]);

    const int j  = tid & 31;       // granule slot within row
    const int r0 = tid >> 5;       // starting row (8 rows per pass)

    // prologue: stage channel 0 into buffer 0
    {
        const float* src = plane0;
        if (j < n8) {
            for (int r = r0; r < H; r += 8)
                cp_async8(smem0 + (unsigned)(r * PITCH_ + 2 * j) * 4u,
                          src + (size_t)r * WA_ + 2 * j);
        }
        cp_commit();
    }

    for (int ch = 0; ch < C_; ++ch) {
        const unsigned sbuf_next = ((ch + 1) & 1) ? smem1 : smem0;
        if (ch + 1 < C_) {
            const float* src = plane0 + (size_t)(ch + 1) * PLANE_;
            if (j < n8) {
                for (int r = r0; r < H; r += 8)
                    cp_async8(sbuf_next + (unsigned)(r * PITCH_ + 2 * j) * 4u,
                              src + (size_t)r * WA_ + 2 * j);
            }
            cp_commit();
            cp_wait1();
        } else {
            cp_wait0();
        }
        __syncthreads();

        const float* tb = (ch & 1) ? tile[1] : tile[0];
        float* outc = outp + (size_t)ch * POS_;
        #pragma unroll
        for (int k = 0; k < PPT_; ++k) {
            const float v00 = tb[o00[k]];
            const float v10 = tb[o10[k]];
            const float v01 = tb[o01[k]];
            const float v11 = tb[o11[k]];
            outc[k * THREADS_ + tid] =
                v00 * w00[k] + v10 * w10[k] + v01 * w01[k] + v11 * w11[k];
        }
        __syncthreads();   // buffer reuse safety before next prefetch overwrites
    }
}

extern "C" void kernel_launch(void* const* d_in, const int* in_sizes, int n_in,
                              void* d_out, int out_size) {
    const float* aer_feat = (const float*)d_in[0];
    const float* pose_uvr = (const float*)d_in[1];
    float* out = (float*)d_out;

    dim3 grid(N_, B_);
    dim3 block(THREADS_);
    aerial_patch_sampler_kernel<<<grid, block>>>(aer_feat, pose_uvr, out);
}